// round 11
// baseline (speedup 1.0000x reference)
#include <cuda_runtime.h>

#define NT 2
#define NPER 256
#define FIT_IN 1600
#define FH 240
#define BB 4
#define NROWS 2048
#define NKNOT 129           // knots; interp rows 0..127
#define NROWT 128
#define SMIN (-8.f)
#define INVH 8.f

__device__ __align__(16) float g_DR[(size_t)NROWS * FIT_IN];
// interleaved table: [e][row][g] -> float2 {G_k[g], G_{k+1}[g]}
__device__ __align__(16) float g_tab[(size_t)4 * NROWT * 200];

__device__ __forceinline__ float tanhe(float x) {
    float xa = fminf(fmaxf(x, -15.f), 15.f);
    float t = __expf(2.f * xa);
    return __fdividef(t - 1.f, t + 1.f);
}
__device__ __forceinline__ unsigned smaddr(const void* p) {
    unsigned a;
    asm("{.reg .u64 t; cvta.to.shared.u64 t, %1; cvt.u32.u64 %0, t;}" : "=r"(a) : "l"(p));
    return a;
}
__device__ __forceinline__ void cp16(unsigned dst, const void* src) {
    asm volatile("cp.async.ca.shared.global [%0], [%1], 16;" :: "r"(dst), "l"(src));
}
__device__ __forceinline__ void cp_commit() {
    asm volatile("cp.async.commit_group;" ::: "memory");
}

// ============ Kernel 0: tabulate G(s); 64 knots x 4 g-quarters per block ====
#define TW0 0
#define TB0 28
#define TW1 56      // [25][50]
#define TB1 1308
#define TW2 1360    // [50][104]
#define TB2 6560
#define T_SMEM 6660

__global__ void __launch_bounds__(256) build_table_kernel(
    const float* __restrict__ eW0, const float* __restrict__ eB0,
    const float* __restrict__ eW1, const float* __restrict__ eB1,
    const float* __restrict__ eW2, const float* __restrict__ eB2)
{
    extern __shared__ float sm[];
    const int t = threadIdx.x;
    const int e = blockIdx.y;
    if (t < 25) { sm[TW0 + t] = eW0[e * 25 + t]; sm[TB0 + t] = eB0[e * 25 + t]; }
    for (int x = t; x < 1250; x += 256) sm[TW1 + x] = eW1[e * 1250 + x];
    if (t < 50) sm[TB1 + t] = eB1[e * 50 + t];
    for (int x = t; x < 5000; x += 256) { int k = x / 100, g = x - 100 * k; sm[TW2 + k * 104 + g] = eW2[e * 5000 + x]; }
    if (t < 100) sm[TB2 + t] = eB2[e * 100 + t];
    __syncthreads();

    const int kq = t >> 2;            // knot within block (0..63)
    const int q  = t & 3;             // g-quarter (0..3)
    const int idx = blockIdx.x * 64 + kq;
    if (idx >= NKNOT) return;
    const float s = SMIN + (float)idx * (1.f / INVH);

    float h0[25];
#pragma unroll
    for (int k = 0; k < 25; ++k)
        h0[k] = tanhe(fmaf(s, sm[TW0 + k], sm[TB0 + k]));

    float h1[50];
#pragma unroll
    for (int gp = 0; gp < 25; ++gp) {
        float a0 = sm[TB1 + 2 * gp], a1 = sm[TB1 + 2 * gp + 1];
#pragma unroll
        for (int k = 0; k < 25; ++k) {
            float2 w = *(const float2*)&sm[TW1 + k * 50 + 2 * gp];
            a0 = fmaf(h0[k], w.x, a0);
            a1 = fmaf(h0[k], w.y, a1);
        }
        int q0 = 2 * gp;     if (q0 >= 25) q0 -= 25;
        int q1 = 2 * gp + 1; if (q1 >= 25) q1 -= 25;
        h1[2 * gp]     = tanhe(a0) + h0[q0];
        h1[2 * gp + 1] = tanhe(a1) + h0[q1];
    }

    // g range [25q, 25q+25) never crosses g=50 -> uniform residual offset.
    // float2 alignment: pairs start at EVEN g.
    const int gbase = 25 * q;
    const int roff  = (q >= 2) ? 50 : 0;
    const int podd  = q & 1;
    const int pstart = gbase + podd;
    const int gscal  = podd ? gbase : gbase + 24;
    float* tabe = g_tab + (size_t)e * NROWT * 200;
    const bool wlo = (idx < NROWT);
    const bool whi = (idx > 0);

#pragma unroll 1
    for (int pp = 0; pp < 12; ++pp) {
        const int g = pstart + 2 * pp;
        float a0 = sm[TB2 + g], a1 = sm[TB2 + g + 1];
#pragma unroll
        for (int k = 0; k < 50; ++k) {
            float2 w = *(const float2*)&sm[TW2 + k * 104 + g];
            float hk = h1[k];
            a0 = fmaf(hk, w.x, a0);
            a1 = fmaf(hk, w.y, a1);
        }
        float o0 = tanhe(a0) + h1[g - roff];
        float o1 = tanhe(a1) + h1[g + 1 - roff];
        if (wlo) { tabe[(size_t)idx * 200 + 2 * g] = o0; tabe[(size_t)idx * 200 + 2 * g + 2] = o1; }
        if (whi) { tabe[(size_t)(idx - 1) * 200 + 2 * g + 1] = o0; tabe[(size_t)(idx - 1) * 200 + 2 * g + 3] = o1; }
    }
    {
        const int g = gscal;
        float a0 = sm[TB2 + g];
#pragma unroll
        for (int k = 0; k < 50; ++k)
            a0 = fmaf(h1[k], sm[TW2 + k * 104 + g], a0);
        float o0 = tanhe(a0) + h1[g - roff];
        if (wlo) tabe[(size_t)idx * 200 + 2 * g] = o0;
        if (whi) tabe[(size_t)(idx - 1) * 200 + 2 * g + 1] = o0;
    }
}

// ============ Kernel A: SMEM-resident table, 8 atoms/block ============
// smem (floats): TAB [2][128][200] = 51200, BLK [8][128][4] = 4096 (reused as
// RED/XYZ [8][4][100] = 3200 after einsum), K int[1024], F float[1024]
#define ETAB 0
#define EBLK 51200
#define EKA  55296
#define EFA  56320
#define E_SMEM 57344    // floats = 229376 B -> 1 block/SM

__global__ void __launch_bounds__(256) emb_dr_kernel(const float* __restrict__ Ri)
{
    extern __shared__ float sm[];
    int* smK = (int*)&sm[EKA];
    float* smF = &sm[EFA];
    float* blkS = &sm[EBLK];
    const int t = threadIdx.x;
    const int blk = blockIdx.x;
    const int tile = blk & 31;
    const int b = (blk >> 5) & 3;
    const int i = blk >> 7;
    const int n0 = tile * 8;

    // stage both tables for this i (contiguous region e=2i, 2i+1)
    {
        const float* src = g_tab + (size_t)(2 * i) * NROWT * 200;
        for (int x = t; x < (2 * NROWT * 200) / 4; x += 256)
            cp16(smaddr(&sm[ETAB + 4 * x]), src + 4 * x);
    }
    // stage blk for j=0: 8 atoms x 128 neighbors x float4
    const float* ri0 = Ri + ((size_t)((b * NT + i) * NPER + n0)) * (NT * 128) * 4;
    for (int x = t; x < 1024; x += 256) {
        int a = x >> 7, m = x & 127;
        cp16(smaddr(blkS + 4 * x), ri0 + ((size_t)a * (NT * 128) + m) * 4);
    }
    cp_commit();
    asm volatile("cp.async.wait_group 0;" ::: "memory");
    __syncthreads();

    const int ms = t >> 7;     // m-stream 0/1
    const int gl = t & 127;    // g slot (<100 active)
    float acc[8][4];
#pragma unroll
    for (int a = 0; a < 8; ++a) { acc[a][0] = acc[a][1] = acc[a][2] = acc[a][3] = 0.f; }

#pragma unroll 1
    for (int j = 0; j < NT; ++j) {
        if (j == 1) {
            __syncthreads();   // einsum j=0 reads done
            for (int x = t; x < 1024; x += 256) {
                int a = x >> 7, m = x & 127;
                cp16(smaddr(blkS + 4 * x), ri0 + ((size_t)a * (NT * 128) + 128 + m) * 4);
            }
            cp_commit();
            asm volatile("cp.async.wait_group 0;" ::: "memory");
            __syncthreads();
        }
        // k,f per (atom, neighbor)
        for (int x = t; x < 1024; x += 256) {
            float s = blkS[4 * x];
            float u = fminf(fmaxf((s - SMIN) * INVH, 0.f), 127.999f);
            int kk = (int)u;
            smK[x] = kk * 200;
            smF[x] = u - (float)kk;
        }
        __syncthreads();

        const float* tj = &sm[ETAB] + j * (NROWT * 200);
        if (gl < 100) {
#pragma unroll 1
            for (int a = 0; a < 8; ++a) {
                const int mb = a * 128 + ms * 64;
#pragma unroll 4
                for (int mm = 0; mm < 64; ++mm) {
                    const int m = mb + mm;
                    const float2 v = *(const float2*)&tj[smK[m] + 2 * gl];
                    const float gv = fmaf(smF[m], v.y - v.x, v.x);
                    const float4 bv = *(const float4*)&blkS[4 * m];
                    acc[a][0] = fmaf(bv.x, gv, acc[a][0]);
                    acc[a][1] = fmaf(bv.y, gv, acc[a][1]);
                    acc[a][2] = fmaf(bv.z, gv, acc[a][2]);
                    acc[a][3] = fmaf(bv.w, gv, acc[a][3]);
                }
            }
        }
    }
    __syncthreads();   // einsum done; BLK reusable as RED

    float* RED = blkS; // [a][c][100]
    if (ms == 1 && gl < 100) {
#pragma unroll
        for (int a = 0; a < 8; ++a) {
            RED[a * 400 + 0 * 100 + gl] = acc[a][0];
            RED[a * 400 + 1 * 100 + gl] = acc[a][1];
            RED[a * 400 + 2 * 100 + gl] = acc[a][2];
            RED[a * 400 + 3 * 100 + gl] = acc[a][3];
        }
    }
    __syncthreads();
    if (ms == 0 && gl < 100) {
        const float invn = 1.f / 256.f;
#pragma unroll
        for (int a = 0; a < 8; ++a) {
            RED[a * 400 + 0 * 100 + gl] = (acc[a][0] + RED[a * 400 + 0 * 100 + gl]) * invn;
            RED[a * 400 + 1 * 100 + gl] = (acc[a][1] + RED[a * 400 + 1 * 100 + gl]) * invn;
            RED[a * 400 + 2 * 100 + gl] = (acc[a][2] + RED[a * 400 + 2 * 100 + gl]) * invn;
            RED[a * 400 + 3 * 100 + gl] = (acc[a][3] + RED[a * 400 + 3 * 100 + gl]) * invn;
        }
    }
    __syncthreads();

    // DR outer products
    const int row0 = (i * BB + b) * NPER + n0;
#pragma unroll 1
    for (int a = 0; a < 8; ++a) {
        float* drow = g_DR + (size_t)(row0 + a) * FIT_IN;
        const float* X = RED + a * 400;
        for (int idx = t; idx < FIT_IN; idx += 256) {
            int g = idx >> 4, h = idx & 15;
            float v = X[g] * X[h];
            v = fmaf(X[100 + g], X[100 + h], v);
            v = fmaf(X[200 + g], X[200 + h], v);
            v = fmaf(X[300 + g], X[300 + h], v);
            drow[idx] = v;
        }
    }
}

// ============ Kernel B: fit net, 8-row tiles, 2 blocks/SM ============
#define KT 16
#define SM_DR   0
#define SM_WS   12800
#define SM_ACTA 20480
#define SM_ACTB 22400
#define B_SMEM  24320

#define ROWF2(r, D, WV) \
    acc[r][0] = fmaf(D, WV.x, acc[r][0]); acc[r][1] = fmaf(D, WV.y, acc[r][1]); \
    acc[r][2] = fmaf(D, WV.z, acc[r][2]); acc[r][3] = fmaf(D, WV.w, acc[r][3]);
#define STEP2(WV, D0, D1) ROWF2(0, D0, WV) ROWF2(1, D1, WV)

__device__ __forceinline__ void run_layer8(
    const float* __restrict__ Wg, const float* __restrict__ bg, int K,
    const float* __restrict__ dpan, int dstride,
    float* w_s, const float* __restrict__ res, float* __restrict__ outp,
    int tid, int ry, int c0)
{
    float acc[2][4];
    {
        float4 bv = *(const float4*)&bg[c0];
        acc[0][0] = bv.x; acc[0][1] = bv.y; acc[0][2] = bv.z; acc[0][3] = bv.w;
        acc[1][0] = bv.x; acc[1][1] = bv.y; acc[1][2] = bv.z; acc[1][3] = bv.w;
    }
    const int T = K / KT;

    for (int x = tid; x < KT * 60; x += 256) {
        int kk = x / 60, seg = x - kk * 60;
        cp16(smaddr(w_s + kk * FH + seg * 4), Wg + (size_t)kk * FH + seg * 4);
    }
    cp_commit();

#pragma unroll 1
    for (int t = 0; t < T; ++t) {
        if (t + 1 < T) {
            float* wnext = w_s + ((t + 1) & 1) * (KT * FH);
            const float* wgn = Wg + (size_t)(t + 1) * KT * FH;
            for (int x = tid; x < KT * 60; x += 256) {
                int kk = x / 60, seg = x - kk * 60;
                cp16(smaddr(wnext + kk * FH + seg * 4), wgn + (size_t)kk * FH + seg * 4);
            }
            cp_commit();
            asm volatile("cp.async.wait_group 1;" ::: "memory");
        } else {
            asm volatile("cp.async.wait_group 0;" ::: "memory");
        }
        __syncthreads();

        const float* wt = w_s + (t & 1) * (KT * FH);
        const float* dp = dpan + (size_t)(2 * ry) * dstride + t * KT;
#pragma unroll
        for (int k4 = 0; k4 < KT; k4 += 4) {
            float4 d0 = *(const float4*)(dp + k4);
            float4 d1 = *(const float4*)(dp + dstride + k4);
            float4 wv0 = *(const float4*)(wt + (k4 + 0) * FH + c0);
            float4 wv1 = *(const float4*)(wt + (k4 + 1) * FH + c0);
            float4 wv2 = *(const float4*)(wt + (k4 + 2) * FH + c0);
            float4 wv3 = *(const float4*)(wt + (k4 + 3) * FH + c0);
            STEP2(wv0, d0.x, d1.x)
            STEP2(wv1, d0.y, d1.y)
            STEP2(wv2, d0.z, d1.z)
            STEP2(wv3, d0.w, d1.w)
        }
        __syncthreads();
    }

#pragma unroll
    for (int r = 0; r < 2; ++r) {
        int row = 2 * ry + r;
        float4 o;
        o.x = tanhe(acc[r][0]); o.y = tanhe(acc[r][1]);
        o.z = tanhe(acc[r][2]); o.w = tanhe(acc[r][3]);
        if (res) {
            float4 rv = *(const float4*)&res[row * FH + c0];
            o.x += rv.x; o.y += rv.y; o.z += rv.z; o.w += rv.w;
        }
        *(float4*)&outp[row * FH + c0] = o;
    }
}

__global__ void __launch_bounds__(256, 2) fit_kernel(
    const float* __restrict__ W0, const float* __restrict__ b0,
    const float* __restrict__ W1, const float* __restrict__ b1,
    const float* __restrict__ W2, const float* __restrict__ b2,
    const float* __restrict__ W3, const float* __restrict__ b3,
    float* __restrict__ out)
{
    extern __shared__ float sm[];
    float* dr   = sm + SM_DR;
    float* w_s  = sm + SM_WS;
    float* actA = sm + SM_ACTA;
    float* actB = sm + SM_ACTB;

    const int tid = threadIdx.x;
    const int i = blockIdx.x >> 7;
    const int r0 = (blockIdx.x & 127) * 8;
    const int ry = tid >> 6;
    const int cx = tid & 63;
    const int cc = (cx < 60) ? cx : 59;
    const int c0 = cc * 4;

    const float* W0g = W0 + (size_t)i * FIT_IN * FH;
    const float* W1g = W1 + (size_t)i * FH * FH;
    const float* W2g = W2 + (size_t)i * FH * FH;
    const float* W3g = W3 + (size_t)i * FH;
    const float* b0g = b0 + i * FH;
    const float* b1g = b1 + i * FH;
    const float* b2g = b2 + i * FH;
    const float  b3v = b3[i];

    {
        const float* drg = g_DR + (size_t)(i * (BB * NPER) + r0) * FIT_IN;
        for (int x = tid; x < (8 * FIT_IN) / 4; x += 256)
            cp16(smaddr(dr + 4 * x), drg + 4 * x);
        cp_commit();
    }

    run_layer8(W0g, b0g, FIT_IN, dr, FIT_IN, w_s, nullptr, actA, tid, ry, c0);
    __syncthreads();
    run_layer8(W1g, b1g, FH, actA, FH, w_s, actA, actB, tid, ry, c0);
    __syncthreads();
    run_layer8(W2g, b2g, FH, actB, FH, w_s, actB, actA, tid, ry, c0);
    __syncthreads();

    const int wi = tid >> 5, lane = tid & 31;
    float p = 0.f;
    for (int o2 = lane; o2 < FH; o2 += 32) p = fmaf(actA[wi * FH + o2], W3g[o2], p);
#pragma unroll
    for (int sd = 16; sd > 0; sd >>= 1) p += __shfl_down_sync(0xffffffffu, p, sd);
    if (lane == 0) {
        int rowg = r0 + wi;
        int bb = rowg >> 8, nn = rowg & 255;
        out[(bb * NT + i) * NPER + nn] = p + b3v;
    }
}

// ---------------- launch ----------------
extern "C" void kernel_launch(void* const* d_in, const int* in_sizes, int n_in,
                              void* d_out, int out_size) {
    const float* Ri  = (const float*)d_in[0];
    const float* eW0 = (const float*)d_in[1];
    const float* eB0 = (const float*)d_in[2];
    const float* eW1 = (const float*)d_in[3];
    const float* eB1 = (const float*)d_in[4];
    const float* eW2 = (const float*)d_in[5];
    const float* eB2 = (const float*)d_in[6];
    const float* fW0 = (const float*)d_in[7];
    const float* fB0 = (const float*)d_in[8];
    const float* fW1 = (const float*)d_in[9];
    const float* fB1 = (const float*)d_in[10];
    const float* fW2 = (const float*)d_in[11];
    const float* fB2 = (const float*)d_in[12];
    const float* fW3 = (const float*)d_in[13];
    const float* fB3 = (const float*)d_in[14];
    float* out = (float*)d_out;

    cudaFuncSetAttribute(build_table_kernel, cudaFuncAttributeMaxDynamicSharedMemorySize,
                         T_SMEM * 4);
    cudaFuncSetAttribute(emb_dr_kernel, cudaFuncAttributeMaxDynamicSharedMemorySize,
                         E_SMEM * 4);
    cudaFuncSetAttribute(fit_kernel, cudaFuncAttributeMaxDynamicSharedMemorySize,
                         B_SMEM * 4);

    build_table_kernel<<<dim3(3, 4), 256, T_SMEM * 4>>>(eW0, eB0, eW1, eB1, eW2, eB2);
    emb_dr_kernel<<<256, 256, E_SMEM * 4>>>(Ri);
    fit_kernel<<<256, 256, B_SMEM * 4>>>(fW0, fB0, fW1, fB1, fW2, fB2, fW3, fB3, out);
}

// round 14
// speedup vs baseline: 1.1046x; 1.1046x over previous
#include <cuda_runtime.h>

#define NT 2
#define NPER 256
#define FIT_IN 1600
#define FH 240
#define BB 4
#define NROWS 2048
#define NKNOT 129           // knots; interp rows 0..127
#define NROWT 128
#define SMIN (-8.f)
#define INVH 8.f

__device__ __align__(16) float g_DR[(size_t)NROWS * FIT_IN];
// interleaved table: [e][row][g] -> float2 {G_k[g], G_{k+1}[g]}  (102.4 KB total)
__device__ __align__(16) float g_tab[(size_t)4 * NROWT * 200];

__device__ __forceinline__ float tanhe(float x) {
    float xa = fminf(fmaxf(x, -15.f), 15.f);
    float t = __expf(2.f * xa);
    return __fdividef(t - 1.f, t + 1.f);
}
__device__ __forceinline__ unsigned smaddr(const void* p) {
    unsigned a;
    asm("{.reg .u64 t; cvta.to.shared.u64 t, %1; cvt.u32.u64 %0, t;}" : "=r"(a) : "l"(p));
    return a;
}
__device__ __forceinline__ void cp16(unsigned dst, const void* src) {
    asm volatile("cp.async.ca.shared.global [%0], [%1], 16;" :: "r"(dst), "l"(src));
}
__device__ __forceinline__ void cp_commit() {
    asm volatile("cp.async.commit_group;" ::: "memory");
}

// ============ Kernel 0: tabulate G(s); two-phase, 16 knots/block ============
#define TW0 0
#define TB0 28
#define TW1 56      // [25][50]
#define TB1 1308
#define TW2 1360    // [50][104]
#define TB2 6560
#define TH1 6660    // [16][52]
#define T_SMEM 7492

__global__ void __launch_bounds__(256) build_table_kernel(
    const float* __restrict__ eW0, const float* __restrict__ eB0,
    const float* __restrict__ eW1, const float* __restrict__ eB1,
    const float* __restrict__ eW2, const float* __restrict__ eB2)
{
    extern __shared__ float sm[];
    const int t = threadIdx.x;
    const int e = blockIdx.y;
    if (t < 25) { sm[TW0 + t] = eW0[e * 25 + t]; sm[TB0 + t] = eB0[e * 25 + t]; }
    for (int x = t; x < 1250; x += 256) sm[TW1 + x] = eW1[e * 1250 + x];
    if (t < 50) sm[TB1 + t] = eB1[e * 50 + t];
    for (int x = t; x < 5000; x += 256) { int k = x / 100, g = x - 100 * k; sm[TW2 + k * 104 + g] = eW2[e * 5000 + x]; }
    if (t < 100) sm[TB2 + t] = eB2[e * 100 + t];
    __syncthreads();

    const int k0 = blockIdx.x * 16;

    // ---- phase 1: threads 0..15 compute h1[50] for their knot ----
    if (t < 16 && k0 + t < NKNOT) {
        const float s = SMIN + (float)(k0 + t) * (1.f / INVH);
        float h0[25];
#pragma unroll
        for (int k = 0; k < 25; ++k)
            h0[k] = tanhe(fmaf(s, sm[TW0 + k], sm[TB0 + k]));
#pragma unroll
        for (int gp = 0; gp < 25; ++gp) {
            float a0 = sm[TB1 + 2 * gp], a1 = sm[TB1 + 2 * gp + 1];
#pragma unroll
            for (int k = 0; k < 25; ++k) {
                float2 w = *(const float2*)&sm[TW1 + k * 50 + 2 * gp];
                a0 = fmaf(h0[k], w.x, a0);
                a1 = fmaf(h0[k], w.y, a1);
            }
            int q0 = 2 * gp;     if (q0 >= 25) q0 -= 25;
            int q1 = 2 * gp + 1; if (q1 >= 25) q1 -= 25;
            sm[TH1 + t * 52 + 2 * gp]     = tanhe(a0) + h0[q0];
            sm[TH1 + t * 52 + 2 * gp + 1] = tanhe(a1) + h0[q1];
        }
    }
    __syncthreads();

    // ---- phase 2: 16 knots x 100 g = 1600 column tasks over 256 threads ----
    float* tabe = g_tab + (size_t)e * NROWT * 200;
#pragma unroll 1
    for (int task = t; task < 1600; task += 256) {
        const int kk = task / 100;
        const int g = task - 100 * kk;
        const int idx = k0 + kk;
        if (idx >= NKNOT) continue;
        const float* h1p = &sm[TH1 + kk * 52];
        float a = sm[TB2 + g];
#pragma unroll
        for (int k = 0; k < 50; ++k)
            a = fmaf(h1p[k], sm[TW2 + k * 104 + g], a);
        int gr = g; if (gr >= 50) gr -= 50;
        const float o = tanhe(a) + h1p[gr];
        if (idx < NROWT) tabe[(size_t)idx * 200 + 2 * g] = o;          // lo of row idx
        if (idx > 0)     tabe[(size_t)(idx - 1) * 200 + 2 * g + 1] = o; // hi of row idx-1
    }
}

// ============ Kernel A: fused table-interp einsum + DR (R10 form) ============
// smem: blk [128][4], k[128](int), f[128], xyz [4][100]
#define SBLK 0
#define SKI  512
#define SFR  640
#define SXYZ 768
#define A_SMEM 1168

__global__ void __launch_bounds__(128) emb_dr_kernel(const float* __restrict__ Ri)
{
    extern __shared__ float sm[];
    int* smi = (int*)sm;
    const int t = threadIdx.x;
    const int blk = blockIdx.x;
    const int n = blk & 255;
    const int b = (blk >> 8) & 3;
    const int i = blk >> 10;

    const float* ri_base = Ri + ((size_t)((b * NT + i) * NPER + n)) * (NT * 128) * 4;

    float acc0 = 0.f, acc1 = 0.f, acc2 = 0.f, acc3 = 0.f;

#pragma unroll 1
    for (int j = 0; j < NT; ++j) {
        __syncthreads();  // prior einsum reads done before restage
        float4 rv = *(const float4*)(ri_base + (size_t)(j * 128 + t) * 4);
        *(float4*)&sm[SBLK + 4 * t] = rv;
        float u = fminf(fmaxf((rv.x - SMIN) * INVH, 0.f), 127.999f);
        int kk = (int)u;
        smi[SKI + t] = kk;
        sm[SFR + t] = u - (float)kk;
        __syncthreads();

        if (t < 100) {
            const float* tabe = g_tab + (size_t)(i * NT + j) * NROWT * 200;
#pragma unroll 4
            for (int m = 0; m < 128; ++m) {
                const int km = smi[SKI + m];
                const float fm = sm[SFR + m];
                float2 v = *(const float2*)(tabe + (size_t)km * 200 + 2 * t);
                float gv = fmaf(fm, v.y - v.x, v.x);
                float4 bv = *(const float4*)&sm[SBLK + 4 * m];
                acc0 = fmaf(bv.x, gv, acc0);
                acc1 = fmaf(bv.y, gv, acc1);
                acc2 = fmaf(bv.z, gv, acc2);
                acc3 = fmaf(bv.w, gv, acc3);
            }
        }
    }

    if (t < 100) {
        const float invn = 1.f / 256.f;
        sm[SXYZ + 0 * 100 + t] = acc0 * invn;
        sm[SXYZ + 1 * 100 + t] = acc1 * invn;
        sm[SXYZ + 2 * 100 + t] = acc2 * invn;
        sm[SXYZ + 3 * 100 + t] = acc3 * invn;
    }
    __syncthreads();

    const int row = (i * BB + b) * NPER + n;
    float* drow = g_DR + (size_t)row * FIT_IN;
#pragma unroll 1
    for (int o = 0; o < 13; ++o) {
        int idx = t + o * 128;
        if (idx < FIT_IN) {
            int g = idx >> 4, h = idx & 15;
            float a = sm[SXYZ + 0 * 100 + g] * sm[SXYZ + 0 * 100 + h];
            a = fmaf(sm[SXYZ + 1 * 100 + g], sm[SXYZ + 1 * 100 + h], a);
            a = fmaf(sm[SXYZ + 2 * 100 + g], sm[SXYZ + 2 * 100 + h], a);
            a = fmaf(sm[SXYZ + 3 * 100 + g], sm[SXYZ + 3 * 100 + h], a);
            drow[idx] = a;
        }
    }
}

// ============ Kernel B: fit net, 8-row tiles, 2 blocks/SM ============
#define KT 16
#define SM_DR   0
#define SM_WS   12800
#define SM_ACTA 20480
#define SM_ACTB 22400
#define B_SMEM  24320

#define ROWF2(r, D, WV) \
    acc[r][0] = fmaf(D, WV.x, acc[r][0]); acc[r][1] = fmaf(D, WV.y, acc[r][1]); \
    acc[r][2] = fmaf(D, WV.z, acc[r][2]); acc[r][3] = fmaf(D, WV.w, acc[r][3]);
#define STEP2(WV, D0, D1) ROWF2(0, D0, WV) ROWF2(1, D1, WV)

__device__ __forceinline__ void run_layer8(
    const float* __restrict__ Wg, const float* __restrict__ bg, int K,
    const float* __restrict__ dpan, int dstride,
    float* w_s, const float* __restrict__ res, float* __restrict__ outp,
    int tid, int ry, int c0)
{
    float acc[2][4];
    {
        float4 bv = *(const float4*)&bg[c0];
        acc[0][0] = bv.x; acc[0][1] = bv.y; acc[0][2] = bv.z; acc[0][3] = bv.w;
        acc[1][0] = bv.x; acc[1][1] = bv.y; acc[1][2] = bv.z; acc[1][3] = bv.w;
    }
    const int T = K / KT;

    for (int x = tid; x < KT * 60; x += 256) {
        int kk = x / 60, seg = x - kk * 60;
        cp16(smaddr(w_s + kk * FH + seg * 4), Wg + (size_t)kk * FH + seg * 4);
    }
    cp_commit();

#pragma unroll 1
    for (int t = 0; t < T; ++t) {
        if (t + 1 < T) {
            float* wnext = w_s + ((t + 1) & 1) * (KT * FH);
            const float* wgn = Wg + (size_t)(t + 1) * KT * FH;
            for (int x = tid; x < KT * 60; x += 256) {
                int kk = x / 60, seg = x - kk * 60;
                cp16(smaddr(wnext + kk * FH + seg * 4), wgn + (size_t)kk * FH + seg * 4);
            }
            cp_commit();
            asm volatile("cp.async.wait_group 1;" ::: "memory");
        } else {
            asm volatile("cp.async.wait_group 0;" ::: "memory");
        }
        __syncthreads();

        const float* wt = w_s + (t & 1) * (KT * FH);
        const float* dp = dpan + (size_t)(2 * ry) * dstride + t * KT;
#pragma unroll
        for (int k4 = 0; k4 < KT; k4 += 4) {
            float4 d0 = *(const float4*)(dp + k4);
            float4 d1 = *(const float4*)(dp + dstride + k4);
            float4 wv0 = *(const float4*)(wt + (k4 + 0) * FH + c0);
            float4 wv1 = *(const float4*)(wt + (k4 + 1) * FH + c0);
            float4 wv2 = *(const float4*)(wt + (k4 + 2) * FH + c0);
            float4 wv3 = *(const float4*)(wt + (k4 + 3) * FH + c0);
            STEP2(wv0, d0.x, d1.x)
            STEP2(wv1, d0.y, d1.y)
            STEP2(wv2, d0.z, d1.z)
            STEP2(wv3, d0.w, d1.w)
        }
        __syncthreads();
    }

#pragma unroll
    for (int r = 0; r < 2; ++r) {
        int row = 2 * ry + r;
        float4 o;
        o.x = tanhe(acc[r][0]); o.y = tanhe(acc[r][1]);
        o.z = tanhe(acc[r][2]); o.w = tanhe(acc[r][3]);
        if (res) {
            float4 rv = *(const float4*)&res[row * FH + c0];
            o.x += rv.x; o.y += rv.y; o.z += rv.z; o.w += rv.w;
        }
        *(float4*)&outp[row * FH + c0] = o;
    }
}

__global__ void __launch_bounds__(256, 2) fit_kernel(
    const float* __restrict__ W0, const float* __restrict__ b0,
    const float* __restrict__ W1, const float* __restrict__ b1,
    const float* __restrict__ W2, const float* __restrict__ b2,
    const float* __restrict__ W3, const float* __restrict__ b3,
    float* __restrict__ out)
{
    extern __shared__ float sm[];
    float* dr   = sm + SM_DR;
    float* w_s  = sm + SM_WS;
    float* actA = sm + SM_ACTA;
    float* actB = sm + SM_ACTB;

    const int tid = threadIdx.x;
    const int i = blockIdx.x >> 7;
    const int r0 = (blockIdx.x & 127) * 8;
    const int ry = tid >> 6;
    const int cx = tid & 63;
    const int cc = (cx < 60) ? cx : 59;
    const int c0 = cc * 4;

    const float* W0g = W0 + (size_t)i * FIT_IN * FH;
    const float* W1g = W1 + (size_t)i * FH * FH;
    const float* W2g = W2 + (size_t)i * FH * FH;
    const float* W3g = W3 + (size_t)i * FH;
    const float* b0g = b0 + i * FH;
    const float* b1g = b1 + i * FH;
    const float* b2g = b2 + i * FH;
    const float  b3v = b3[i];

    {
        const float* drg = g_DR + (size_t)(i * (BB * NPER) + r0) * FIT_IN;
        for (int x = tid; x < (8 * FIT_IN) / 4; x += 256)
            cp16(smaddr(dr + 4 * x), drg + 4 * x);
        cp_commit();
    }

    run_layer8(W0g, b0g, FIT_IN, dr, FIT_IN, w_s, nullptr, actA, tid, ry, c0);
    __syncthreads();
    run_layer8(W1g, b1g, FH, actA, FH, w_s, actA, actB, tid, ry, c0);
    __syncthreads();
    run_layer8(W2g, b2g, FH, actB, FH, w_s, actB, actA, tid, ry, c0);
    __syncthreads();

    const int wi = tid >> 5, lane = tid & 31;
    float p = 0.f;
    for (int o2 = lane; o2 < FH; o2 += 32) p = fmaf(actA[wi * FH + o2], W3g[o2], p);
#pragma unroll
    for (int sd = 16; sd > 0; sd >>= 1) p += __shfl_down_sync(0xffffffffu, p, sd);
    if (lane == 0) {
        int rowg = r0 + wi;
        int bb = rowg >> 8, nn = rowg & 255;
        out[(bb * NT + i) * NPER + nn] = p + b3v;
    }
}

// ---------------- launch ----------------
extern "C" void kernel_launch(void* const* d_in, const int* in_sizes, int n_in,
                              void* d_out, int out_size) {
    const float* Ri  = (const float*)d_in[0];
    const float* eW0 = (const float*)d_in[1];
    const float* eB0 = (const float*)d_in[2];
    const float* eW1 = (const float*)d_in[3];
    const float* eB1 = (const float*)d_in[4];
    const float* eW2 = (const float*)d_in[5];
    const float* eB2 = (const float*)d_in[6];
    const float* fW0 = (const float*)d_in[7];
    const float* fB0 = (const float*)d_in[8];
    const float* fW1 = (const float*)d_in[9];
    const float* fB1 = (const float*)d_in[10];
    const float* fW2 = (const float*)d_in[11];
    const float* fB2 = (const float*)d_in[12];
    const float* fW3 = (const float*)d_in[13];
    const float* fB3 = (const float*)d_in[14];
    float* out = (float*)d_out;

    cudaFuncSetAttribute(build_table_kernel, cudaFuncAttributeMaxDynamicSharedMemorySize,
                         T_SMEM * 4);
    cudaFuncSetAttribute(emb_dr_kernel, cudaFuncAttributeMaxDynamicSharedMemorySize,
                         A_SMEM * 4);
    cudaFuncSetAttribute(fit_kernel, cudaFuncAttributeMaxDynamicSharedMemorySize,
                         B_SMEM * 4);

    build_table_kernel<<<dim3(9, 4), 256, T_SMEM * 4>>>(eW0, eB0, eW1, eB1, eW2, eB2);
    emb_dr_kernel<<<NROWS, 128, A_SMEM * 4>>>(Ri);
    fit_kernel<<<256, 256, B_SMEM * 4>>>(fW0, fB0, fW1, fB1, fW2, fB2, fW3, fB3, out);
}

// round 17
// speedup vs baseline: 1.6011x; 1.4495x over previous
#include <cuda_runtime.h>

#define NT 2
#define NPER 256
#define FIT_IN 1600
#define FH 240
#define BB 4
#define NROWS 2048
#define NKNOT 129           // knots; interp rows 0..127
#define NROWT 128
#define SMIN (-8.f)
#define INVH 8.f

__device__ __align__(16) float g_DR[(size_t)NROWS * FIT_IN];
// interleaved table: [e][row][g] -> float2 {G_k[g], G_{k+1}[g]}
__device__ __align__(16) float g_tab[(size_t)4 * NROWT * 200];

__device__ __forceinline__ float tanhe(float x) {
    float xa = fminf(fmaxf(x, -15.f), 15.f);
    float t = __expf(2.f * xa);
    return __fdividef(t - 1.f, t + 1.f);
}
__device__ __forceinline__ unsigned smaddr(const void* p) {
    unsigned a;
    asm("{.reg .u64 t; cvta.to.shared.u64 t, %1; cvt.u32.u64 %0, t;}" : "=r"(a) : "l"(p));
    return a;
}
__device__ __forceinline__ void cp16(unsigned dst, const void* src) {
    asm volatile("cp.async.ca.shared.global [%0], [%1], 16;" :: "r"(dst), "l"(src));
}
__device__ __forceinline__ void cp_commit() {
    asm volatile("cp.async.commit_group;" ::: "memory");
}

// ============ Kernel 0: tabulate G(s); fully task-parallel ============
#define TW0 0
#define TB0 28
#define TW1 56      // [25][50]
#define TB1 1308
#define TW2 1360    // [50][104]
#define TB2 6560
#define TH0 6660    // [16][26]
#define TH1 7076    // [16][52]
#define T_SMEM 7908

__global__ void __launch_bounds__(256) build_table_kernel(
    const float* __restrict__ eW0, const float* __restrict__ eB0,
    const float* __restrict__ eW1, const float* __restrict__ eB1,
    const float* __restrict__ eW2, const float* __restrict__ eB2)
{
    extern __shared__ float sm[];
    const int t = threadIdx.x;
    const int e = blockIdx.y;
    if (t < 25) { sm[TW0 + t] = eW0[e * 25 + t]; sm[TB0 + t] = eB0[e * 25 + t]; }
    for (int x = t; x < 1250; x += 256) sm[TW1 + x] = eW1[e * 1250 + x];
    if (t < 50) sm[TB1 + t] = eB1[e * 50 + t];
    for (int x = t; x < 5000; x += 256) { int k = x / 100, g = x - 100 * k; sm[TW2 + k * 104 + g] = eW2[e * 5000 + x]; }
    if (t < 100) sm[TB2 + t] = eB2[e * 100 + t];
    __syncthreads();

    const int k0 = blockIdx.x * 16;

    // phase 1a: h0 — 16 knots x 25 units = 400 tasks
    for (int x = t; x < 400; x += 256) {
        const int kk = x / 25, k = x - 25 * kk;
        if (k0 + kk < NKNOT) {
            const float s = SMIN + (float)(k0 + kk) * (1.f / INVH);
            sm[TH0 + kk * 26 + k] = tanhe(fmaf(s, sm[TW0 + k], sm[TB0 + k]));
        }
    }
    __syncthreads();

    // phase 1b: h1 — 16 knots x 25 gp-pairs = 400 tasks
    for (int x = t; x < 400; x += 256) {
        const int kk = x / 25, gp = x - 25 * kk;
        if (k0 + kk < NKNOT) {
            const float* h0p = &sm[TH0 + kk * 26];
            float a0 = sm[TB1 + 2 * gp], a1 = sm[TB1 + 2 * gp + 1];
#pragma unroll
            for (int k = 0; k < 25; ++k) {
                float2 w = *(const float2*)&sm[TW1 + k * 50 + 2 * gp];
                a0 = fmaf(h0p[k], w.x, a0);
                a1 = fmaf(h0p[k], w.y, a1);
            }
            int q0 = 2 * gp;     if (q0 >= 25) q0 -= 25;
            int q1 = 2 * gp + 1; if (q1 >= 25) q1 -= 25;
            sm[TH1 + kk * 52 + 2 * gp]     = tanhe(a0) + h0p[q0];
            sm[TH1 + kk * 52 + 2 * gp + 1] = tanhe(a1) + h0p[q1];
        }
    }
    __syncthreads();

    // phase 2: 16 knots x 100 g = 1600 column tasks
    float* tabe = g_tab + (size_t)e * NROWT * 200;
#pragma unroll 1
    for (int task = t; task < 1600; task += 256) {
        const int kk = task / 100;
        const int g = task - 100 * kk;
        const int idx = k0 + kk;
        if (idx >= NKNOT) continue;
        const float* h1p = &sm[TH1 + kk * 52];
        float a = sm[TB2 + g];
#pragma unroll
        for (int k = 0; k < 50; ++k)
            a = fmaf(h1p[k], sm[TW2 + k * 104 + g], a);
        int gr = g; if (gr >= 50) gr -= 50;
        const float o = tanhe(a) + h1p[gr];
        if (idx < NROWT) tabe[(size_t)idx * 200 + 2 * g] = o;
        if (idx > 0)     tabe[(size_t)(idx - 1) * 200 + 2 * g + 1] = o;
    }
}

// ============ Kernel A: fused table-interp einsum + DR ============
// smem: blk [128][4], kf int2[128], xyz [4][100]
#define SBLK 0
#define SKF  512
#define SXYZ 768
#define A_SMEM 1168

__global__ void __launch_bounds__(128) emb_dr_kernel(const float* __restrict__ Ri)
{
    extern __shared__ float sm[];
    int2* skf = (int2*)&sm[SKF];
    const int t = threadIdx.x;
    const int blk = blockIdx.x;
    const int n = blk & 255;
    const int b = (blk >> 8) & 3;
    const int i = blk >> 10;

    const float* ri_base = Ri + ((size_t)((b * NT + i) * NPER + n)) * (NT * 128) * 4;

    float acc0 = 0.f, acc1 = 0.f, acc2 = 0.f, acc3 = 0.f;

#pragma unroll 1
    for (int j = 0; j < NT; ++j) {
        __syncthreads();  // prior einsum reads done before restage
        float4 rv = *(const float4*)(ri_base + (size_t)(j * 128 + t) * 4);
        *(float4*)&sm[SBLK + 4 * t] = rv;
        float u = fminf(fmaxf((rv.x - SMIN) * INVH, 0.f), 127.999f);
        int kk = (int)u;
        skf[t] = make_int2(kk * 200, __float_as_int(u - (float)kk));
        __syncthreads();

        if (t < 100) {
            const float* tabe = g_tab + (size_t)(i * NT + j) * NROWT * 200;
#pragma unroll 4
            for (int m = 0; m < 128; ++m) {
                const int2 kf = skf[m];
                const float fm = __int_as_float(kf.y);
                float2 v = *(const float2*)(tabe + kf.x + 2 * t);
                float gv = fmaf(fm, v.y - v.x, v.x);
                float4 bv = *(const float4*)&sm[SBLK + 4 * m];
                acc0 = fmaf(bv.x, gv, acc0);
                acc1 = fmaf(bv.y, gv, acc1);
                acc2 = fmaf(bv.z, gv, acc2);
                acc3 = fmaf(bv.w, gv, acc3);
            }
        }
    }

    if (t < 100) {
        const float invn = 1.f / 256.f;
        sm[SXYZ + 0 * 100 + t] = acc0 * invn;
        sm[SXYZ + 1 * 100 + t] = acc1 * invn;
        sm[SXYZ + 2 * 100 + t] = acc2 * invn;
        sm[SXYZ + 3 * 100 + t] = acc3 * invn;
    }
    __syncthreads();

    const int row = (i * BB + b) * NPER + n;
    float* drow = g_DR + (size_t)row * FIT_IN;
#pragma unroll 1
    for (int o = 0; o < 13; ++o) {
        int idx = t + o * 128;
        if (idx < FIT_IN) {
            int g = idx >> 4, h = idx & 15;
            float a = sm[SXYZ + 0 * 100 + g] * sm[SXYZ + 0 * 100 + h];
            a = fmaf(sm[SXYZ + 1 * 100 + g], sm[SXYZ + 1 * 100 + h], a);
            a = fmaf(sm[SXYZ + 2 * 100 + g], sm[SXYZ + 2 * 100 + h], a);
            a = fmaf(sm[SXYZ + 3 * 100 + g], sm[SXYZ + 3 * 100 + h], a);
            drow[idx] = a;
        }
    }
}

// ============ Kernel B: fit net — 16-row tiles, 8x4 thread tiles ============
#define KT 16
#define SM_DR   0                      // 16*1600 = 25600
#define SM_WS   25600                  // 2*16*240 = 7680
#define SM_ACTA 33280                  // 16*240 = 3840
#define SM_ACTB 37120
#define B_SMEM  40960                  // floats = 163840 B

__device__ __forceinline__ void run_layer16(
    const float* __restrict__ Wg, const float* __restrict__ bg, int K,
    const float* __restrict__ dpan, int dstride,
    float* w_s, const float* __restrict__ res, float* __restrict__ outp,
    int tid, int ry, int c0)
{
    float acc[8][4];
    {
        float4 bv = *(const float4*)&bg[c0];
#pragma unroll
        for (int r = 0; r < 8; ++r) {
            acc[r][0] = bv.x; acc[r][1] = bv.y; acc[r][2] = bv.z; acc[r][3] = bv.w;
        }
    }
    const int T = K / KT;

    for (int x = tid; x < KT * 60; x += 128) {
        int kk = x / 60, seg = x - kk * 60;
        cp16(smaddr(w_s + kk * FH + seg * 4), Wg + (size_t)kk * FH + seg * 4);
    }
    cp_commit();

#pragma unroll 1
    for (int t = 0; t < T; ++t) {
        if (t + 1 < T) {
            float* wnext = w_s + ((t + 1) & 1) * (KT * FH);
            const float* wgn = Wg + (size_t)(t + 1) * KT * FH;
            for (int x = tid; x < KT * 60; x += 128) {
                int kk = x / 60, seg = x - kk * 60;
                cp16(smaddr(wnext + kk * FH + seg * 4), wgn + (size_t)kk * FH + seg * 4);
            }
            cp_commit();
            asm volatile("cp.async.wait_group 1;" ::: "memory");
        } else {
            asm volatile("cp.async.wait_group 0;" ::: "memory");
        }
        __syncthreads();

        const float* wt = w_s + (t & 1) * (KT * FH);
        const float* dp = dpan + (size_t)(8 * ry) * dstride + t * KT;
#pragma unroll
        for (int k4 = 0; k4 < KT; k4 += 4) {
            float4 d[8];
#pragma unroll
            for (int r = 0; r < 8; ++r)
                d[r] = *(const float4*)(dp + r * dstride + k4);
            float4 wv0 = *(const float4*)(wt + (k4 + 0) * FH + c0);
            float4 wv1 = *(const float4*)(wt + (k4 + 1) * FH + c0);
            float4 wv2 = *(const float4*)(wt + (k4 + 2) * FH + c0);
            float4 wv3 = *(const float4*)(wt + (k4 + 3) * FH + c0);
#pragma unroll
            for (int r = 0; r < 8; ++r) {
                acc[r][0] = fmaf(d[r].x, wv0.x, acc[r][0]);
                acc[r][1] = fmaf(d[r].x, wv0.y, acc[r][1]);
                acc[r][2] = fmaf(d[r].x, wv0.z, acc[r][2]);
                acc[r][3] = fmaf(d[r].x, wv0.w, acc[r][3]);
                acc[r][0] = fmaf(d[r].y, wv1.x, acc[r][0]);
                acc[r][1] = fmaf(d[r].y, wv1.y, acc[r][1]);
                acc[r][2] = fmaf(d[r].y, wv1.z, acc[r][2]);
                acc[r][3] = fmaf(d[r].y, wv1.w, acc[r][3]);
                acc[r][0] = fmaf(d[r].z, wv2.x, acc[r][0]);
                acc[r][1] = fmaf(d[r].z, wv2.y, acc[r][1]);
                acc[r][2] = fmaf(d[r].z, wv2.z, acc[r][2]);
                acc[r][3] = fmaf(d[r].z, wv2.w, acc[r][3]);
                acc[r][0] = fmaf(d[r].w, wv3.x, acc[r][0]);
                acc[r][1] = fmaf(d[r].w, wv3.y, acc[r][1]);
                acc[r][2] = fmaf(d[r].w, wv3.z, acc[r][2]);
                acc[r][3] = fmaf(d[r].w, wv3.w, acc[r][3]);
            }
        }
        __syncthreads();
    }

    // epilogue; col-threads cx>=60 duplicate group 59 (benign identical writes)
#pragma unroll
    for (int r = 0; r < 8; ++r) {
        int row = 8 * ry + r;
        float4 o;
        o.x = tanhe(acc[r][0]); o.y = tanhe(acc[r][1]);
        o.z = tanhe(acc[r][2]); o.w = tanhe(acc[r][3]);
        if (res) {
            float4 rv = *(const float4*)&res[row * FH + c0];
            o.x += rv.x; o.y += rv.y; o.z += rv.z; o.w += rv.w;
        }
        *(float4*)&outp[row * FH + c0] = o;
    }
}

__global__ void __launch_bounds__(128, 1) fit_kernel(
    const float* __restrict__ W0, const float* __restrict__ b0,
    const float* __restrict__ W1, const float* __restrict__ b1,
    const float* __restrict__ W2, const float* __restrict__ b2,
    const float* __restrict__ W3, const float* __restrict__ b3,
    float* __restrict__ out)
{
    extern __shared__ float sm[];
    float* dr   = sm + SM_DR;
    float* w_s  = sm + SM_WS;
    float* actA = sm + SM_ACTA;
    float* actB = sm + SM_ACTB;

    const int tid = threadIdx.x;
    const int i = blockIdx.x >> 6;
    const int r0 = (blockIdx.x & 63) * 16;
    const int ry = tid >> 6;               // 2 row-groups of 8 rows
    const int cx = tid & 63;
    const int cc = (cx < 60) ? cx : 59;
    const int c0 = cc * 4;

    const float* W0g = W0 + (size_t)i * FIT_IN * FH;
    const float* W1g = W1 + (size_t)i * FH * FH;
    const float* W2g = W2 + (size_t)i * FH * FH;
    const float* W3g = W3 + (size_t)i * FH;
    const float* b0g = b0 + i * FH;
    const float* b1g = b1 + i * FH;
    const float* b2g = b2 + i * FH;
    const float  b3v = b3[i];

    {
        const float* drg = g_DR + (size_t)(i * (BB * NPER) + r0) * FIT_IN;
        for (int x = tid; x < (16 * FIT_IN) / 4; x += 128)
            cp16(smaddr(dr + 4 * x), drg + 4 * x);
        cp_commit();
    }

    run_layer16(W0g, b0g, FIT_IN, dr, FIT_IN, w_s, nullptr, actA, tid, ry, c0);
    __syncthreads();
    run_layer16(W1g, b1g, FH, actA, FH, w_s, actA, actB, tid, ry, c0);
    __syncthreads();
    run_layer16(W2g, b2g, FH, actB, FH, w_s, actB, actA, tid, ry, c0);
    __syncthreads();

    // final 240 -> 1: 4 warps x 4 rows each
    const int wi = tid >> 5, lane = tid & 31;
#pragma unroll 1
    for (int rr = 0; rr < 4; ++rr) {
        int r = wi * 4 + rr;
        float p = 0.f;
        for (int o2 = lane; o2 < FH; o2 += 32) p = fmaf(actA[r * FH + o2], W3g[o2], p);
#pragma unroll
        for (int sd = 16; sd > 0; sd >>= 1) p += __shfl_down_sync(0xffffffffu, p, sd);
        if (lane == 0) {
            int rowg = r0 + r;
            int bb = rowg >> 8, nn = rowg & 255;
            out[(bb * NT + i) * NPER + nn] = p + b3v;
        }
    }
}

// ---------------- launch ----------------
extern "C" void kernel_launch(void* const* d_in, const int* in_sizes, int n_in,
                              void* d_out, int out_size) {
    const float* Ri  = (const float*)d_in[0];
    const float* eW0 = (const float*)d_in[1];
    const float* eB0 = (const float*)d_in[2];
    const float* eW1 = (const float*)d_in[3];
    const float* eB1 = (const float*)d_in[4];
    const float* eW2 = (const float*)d_in[5];
    const float* eB2 = (const float*)d_in[6];
    const float* fW0 = (const float*)d_in[7];
    const float* fB0 = (const float*)d_in[8];
    const float* fW1 = (const float*)d_in[9];
    const float* fB1 = (const float*)d_in[10];
    const float* fW2 = (const float*)d_in[11];
    const float* fB2 = (const float*)d_in[12];
    const float* fW3 = (const float*)d_in[13];
    const float* fB3 = (const float*)d_in[14];
    float* out = (float*)d_out;

    cudaFuncSetAttribute(build_table_kernel, cudaFuncAttributeMaxDynamicSharedMemorySize,
                         T_SMEM * 4);
    cudaFuncSetAttribute(emb_dr_kernel, cudaFuncAttributeMaxDynamicSharedMemorySize,
                         A_SMEM * 4);
    cudaFuncSetAttribute(fit_kernel, cudaFuncAttributeMaxDynamicSharedMemorySize,
                         B_SMEM * 4);

    build_table_kernel<<<dim3(9, 4), 256, T_SMEM * 4>>>(eW0, eB0, eW1, eB1, eW2, eB2);
    emb_dr_kernel<<<NROWS, 128, A_SMEM * 4>>>(Ri);
    fit_kernel<<<128, 128, B_SMEM * 4>>>(fW0, fB0, fW1, fB1, fW2, fB2, fW3, fB3, out);
}